// round 9
// baseline (speedup 1.0000x reference)
#include <cuda_runtime.h>
#include <cstdint>

static constexpr int BDIM = 4096;
static constexpr int IDIM = 1024;
static constexpr int HDIM = 2048;
static constexpr int NSTEPS = 10;
static constexpr float DT = 0.1f;

static constexpr int BM = 128, BN = 64, BK = 64;   // BK in s8 elements (64 B rows)
static constexpr int STAGES = 4;
static constexpr int NT = 256;
// stage: [A1 8K | A0 8K | B1 4K | B0 4K] = 24 KB
static constexpr int A_PLANE = BM * BK;            // 8 KB
static constexpr int B_PLANE = BN * BK;            // 4 KB
static constexpr int STAGE_BYTES = 2 * A_PLANE + 2 * B_PLANE;   // 24 KB
static constexpr int OFF_BPL = 2 * A_PLANE;
static constexpr int OFF_SDEC = STAGES * STAGE_BYTES;           // 96 KB
static constexpr int OFF_SSAB = OFF_SDEC + BN * 4;
static constexpr int SMEM_TOTAL = OFF_SSAB + BN * 4 + 16;

static constexpr float QMAX = 16256.0f;   // 127*128

// quantized planes: [plane][rows][K]; plane0 = q1(hi), plane1 = q0(lo)
__device__ int8_t g_xq  [2 * BDIM * IDIM];
__device__ int8_t g_wihq[2 * HDIM * IDIM];
__device__ int8_t g_whhq[2 * HDIM * HDIM];
__device__ int8_t g_hqA [2 * BDIM * HDIM];
__device__ int8_t g_hqB [2 * BDIM * HDIM];
__device__ float g_ihb  [BDIM * HDIM];
__device__ float g_hfull[BDIM * HDIM];
__device__ float g_swih[HDIM];   // per-row scale of Wih
__device__ float g_iswih[HDIM];
__device__ float g_swhh[HDIM];
__device__ float g_iswhh[HDIM];
__device__ int   g_maxx_bits;
__device__ int   g_maxh_bits;

__device__ __forceinline__ uint32_t smem_u32(const void* p) {
    uint32_t a;
    asm("{ .reg .u64 t; cvta.to.shared.u64 t, %1; cvt.u32.u64 %0, t; }" : "=r"(a) : "l"(p));
    return a;
}
__device__ __forceinline__ void cp16(uint32_t dst, const void* src) {
    asm volatile("cp.async.cg.shared.global [%0], [%1], 16;" :: "r"(dst), "l"(src) : "memory");
}
__device__ __forceinline__ void cp_commit() { asm volatile("cp.async.commit_group;" ::: "memory"); }
template <int N> __device__ __forceinline__ void cp_wait() {
    asm volatile("cp.async.wait_group %0;" :: "n"(N) : "memory");
}
__device__ __forceinline__ float tanh_acc(float x) {
    float ax = fabsf(x);
    float e = __expf(-2.0f * ax);
    float t = (1.0f - e) / (1.0f + e);
    return copysignf(t, x);
}
__device__ __forceinline__ void imma(int* c, const uint32_t* a, const uint32_t* b) {
    asm volatile(
        "mma.sync.aligned.m16n8k32.row.col.s32.s8.s8.s32 "
        "{%0,%1,%2,%3},{%4,%5,%6,%7},{%8,%9},{%0,%1,%2,%3};"
        : "+r"(c[0]), "+r"(c[1]), "+r"(c[2]), "+r"(c[3])
        : "r"(a[0]), "r"(a[1]), "r"(a[2]), "r"(a[3]), "r"(b[0]), "r"(b[1]));
}
__device__ __forceinline__ void ldsm4(uint32_t* r, uint32_t addr) {
    asm volatile("ldmatrix.sync.aligned.m8n8.x4.shared.b16 {%0,%1,%2,%3}, [%4];"
                 : "=r"(r[0]), "=r"(r[1]), "=r"(r[2]), "=r"(r[3]) : "r"(addr));
}
// v -> q1*128 + q0 with q = rn(v*inv_s) clamped to [-16256,16256]
__device__ __forceinline__ void quant1(float v, float inv_s, int8_t& c1, int8_t& c0) {
    int q = __float2int_rn(v * inv_s);
    q = max(-16256, min(16256, q));
    int hi = (q + 64) >> 7;
    c1 = (int8_t)hi;
    c0 = (int8_t)(q - (hi << 7));
}
struct s8x4 { int8_t x, y, z, w; };

// ---------------------------------------------------------------------------
__global__ void init_scales_kernel() {
    if (threadIdx.x == 0) { g_maxx_bits = 0; g_maxh_bits = 0; }
}

// 512 blocks x 256: global maxes of |x|,|h0| + per-row maxes of Whh/Wih
__global__ void reduce_scales_kernel(const float* __restrict__ x,
                                     const float* __restrict__ h0,
                                     const float* __restrict__ Wih,
                                     const float* __restrict__ Whh) {
    __shared__ float red[8];
    const int tid = threadIdx.x;
    const int gtid = blockIdx.x * blockDim.x + tid;
    const int stride = gridDim.x * blockDim.x;
    const int lane = tid & 31, wid = tid >> 5;

    float mx = 0.0f;
    for (int i = gtid; i < BDIM * IDIM / 4; i += stride) {
        float4 v = reinterpret_cast<const float4*>(x)[i];
        mx = fmaxf(mx, fmaxf(fmaxf(fabsf(v.x), fabsf(v.y)), fmaxf(fabsf(v.z), fabsf(v.w))));
    }
    float mh = 0.0f;
    for (int i = gtid; i < BDIM * HDIM / 4; i += stride) {
        float4 v = reinterpret_cast<const float4*>(h0)[i];
        mh = fmaxf(mh, fmaxf(fmaxf(fabsf(v.x), fabsf(v.y)), fmaxf(fabsf(v.z), fabsf(v.w))));
    }
    #pragma unroll
    for (int o = 16; o > 0; o >>= 1) {
        mx = fmaxf(mx, __shfl_xor_sync(0xFFFFFFFF, mx, o));
        mh = fmaxf(mh, __shfl_xor_sync(0xFFFFFFFF, mh, o));
    }
    if (lane == 0) red[wid] = mx;
    __syncthreads();
    if (wid == 0) {
        float v = (lane < 8) ? red[lane] : 0.0f;
        #pragma unroll
        for (int o = 4; o > 0; o >>= 1) v = fmaxf(v, __shfl_xor_sync(0xFFFFFFFF, v, o));
        if (lane == 0) atomicMax(&g_maxx_bits, __float_as_int(v));
    }
    __syncthreads();
    if (lane == 0) red[wid] = mh;
    __syncthreads();
    if (wid == 0) {
        float v = (lane < 8) ? red[lane] : 0.0f;
        #pragma unroll
        for (int o = 4; o > 0; o >>= 1) v = fmaxf(v, __shfl_xor_sync(0xFFFFFFFF, v, o));
        if (lane == 0) atomicMax(&g_maxh_bits, __float_as_int(v));
    }
    // per-row W maxes: global warp id = row
    const int gw = blockIdx.x * 8 + wid;
    if (gw < HDIM) {   // Whh row gw (2048 elems)
        float m = 0.0f;
        const float4* row = reinterpret_cast<const float4*>(Whh + (size_t)gw * HDIM);
        for (int i = lane; i < HDIM / 4; i += 32) {
            float4 v = row[i];
            m = fmaxf(m, fmaxf(fmaxf(fabsf(v.x), fabsf(v.y)), fmaxf(fabsf(v.z), fabsf(v.w))));
        }
        #pragma unroll
        for (int o = 16; o > 0; o >>= 1) m = fmaxf(m, __shfl_xor_sync(0xFFFFFFFF, m, o));
        if (lane == 0) {
            m = fmaxf(m, 1e-30f);
            g_swhh[gw] = m * (1.0f / QMAX);
            g_iswhh[gw] = QMAX / m;
        }
    } else if (gw < 2 * HDIM) {   // Wih row (1024 elems)
        const int r = gw - HDIM;
        float m = 0.0f;
        const float4* row = reinterpret_cast<const float4*>(Wih + (size_t)r * IDIM);
        for (int i = lane; i < IDIM / 4; i += 32) {
            float4 v = row[i];
            m = fmaxf(m, fmaxf(fmaxf(fabsf(v.x), fabsf(v.y)), fmaxf(fabsf(v.z), fabsf(v.w))));
        }
        #pragma unroll
        for (int o = 16; o > 0; o >>= 1) m = fmaxf(m, __shfl_xor_sync(0xFFFFFFFF, m, o));
        if (lane == 0) {
            m = fmaxf(m, 1e-30f);
            g_swih[r] = m * (1.0f / QMAX);
            g_iswih[r] = QMAX / m;
        }
    }
}

__global__ void quant_all_kernel(const float* __restrict__ x,
                                 const float* __restrict__ h0,
                                 const float* __restrict__ Wih,
                                 const float* __restrict__ Whh) {
    const int stride = gridDim.x * blockDim.x;
    const int t0 = blockIdx.x * blockDim.x + threadIdx.x;
    const float inv_sx = QMAX / fmaxf(__int_as_float(g_maxx_bits), 1e-30f);
    const float inv_sh = QMAX / fmaxf(__int_as_float(g_maxh_bits), 1.0f);

    for (int i = t0; i < BDIM * IDIM / 4; i += stride) {
        float4 v = reinterpret_cast<const float4*>(x)[i];
        s8x4 c1, c0;
        quant1(v.x, inv_sx, c1.x, c0.x); quant1(v.y, inv_sx, c1.y, c0.y);
        quant1(v.z, inv_sx, c1.z, c0.z); quant1(v.w, inv_sx, c1.w, c0.w);
        reinterpret_cast<s8x4*>(g_xq)[i] = c1;
        reinterpret_cast<s8x4*>(g_xq + BDIM * IDIM)[i] = c0;
    }
    for (int i = t0; i < HDIM * IDIM / 4; i += stride) {
        float4 v = reinterpret_cast<const float4*>(Wih)[i];
        const float is = g_iswih[(i * 4) / IDIM];
        s8x4 c1, c0;
        quant1(v.x, is, c1.x, c0.x); quant1(v.y, is, c1.y, c0.y);
        quant1(v.z, is, c1.z, c0.z); quant1(v.w, is, c1.w, c0.w);
        reinterpret_cast<s8x4*>(g_wihq)[i] = c1;
        reinterpret_cast<s8x4*>(g_wihq + HDIM * IDIM)[i] = c0;
    }
    for (int i = t0; i < HDIM * HDIM / 4; i += stride) {
        float4 v = reinterpret_cast<const float4*>(Whh)[i];
        const float is = g_iswhh[(i * 4) / HDIM];
        s8x4 c1, c0;
        quant1(v.x, is, c1.x, c0.x); quant1(v.y, is, c1.y, c0.y);
        quant1(v.z, is, c1.z, c0.z); quant1(v.w, is, c1.w, c0.w);
        reinterpret_cast<s8x4*>(g_whhq)[i] = c1;
        reinterpret_cast<s8x4*>(g_whhq + HDIM * HDIM)[i] = c0;
    }
    for (int i = t0; i < BDIM * HDIM / 4; i += stride) {
        float4 v = reinterpret_cast<const float4*>(h0)[i];
        reinterpret_cast<float4*>(g_hfull)[i] = v;
        s8x4 c1, c0;
        quant1(v.x, inv_sh, c1.x, c0.x); quant1(v.y, inv_sh, c1.y, c0.y);
        quant1(v.z, inv_sh, c1.z, c0.z); quant1(v.w, inv_sh, c1.w, c0.w);
        reinterpret_cast<s8x4*>(g_hqA)[i] = c1;
        reinterpret_cast<s8x4*>(g_hqA + BDIM * HDIM)[i] = c0;
    }
}

// D[m][n] = sa*sb[n]*(16384*S11 + 128*(S10+S01)); int accumulation exact.
template <bool STEP>
__global__ __launch_bounds__(NT, 2)
void gemm_kernel(const int8_t* __restrict__ Aq,   // planes: [0]=q1, [plane_sz]=q0
                 const int8_t* __restrict__ Wq,
                 int K,
                 const float* __restrict__ aux0,   // STEP: ihb      | !STEP: b_ih
                 const float* __restrict__ aux1,   // STEP: hfull_in | !STEP: b_hh
                 const float* __restrict__ tau,
                 const float* __restrict__ sbv,    // per-col (n) W scale
                 float* __restrict__ out_full,
                 int8_t* __restrict__ out_q,       // planes
                 int ldo) {
    extern __shared__ char sm[];
    float* sdec = (float*)(sm + OFF_SDEC);
    float* ssab = (float*)(sm + OFF_SSAB);
    const uint32_t sb = smem_u32(sm);
    const int tid = threadIdx.x;
    const int lane = tid & 31;
    const int wid = tid >> 5;
    const int wm = wid >> 2;
    const int wn = wid & 3;
    const int g = lane >> 2;
    const int tig = lane & 3;
    const int n0 = blockIdx.x * BN;
    const int m0 = blockIdx.y * BM;
    const size_t aplane = (size_t)(STEP ? BDIM * HDIM : BDIM * IDIM);
    const size_t wplane = (size_t)(STEP ? HDIM * HDIM : HDIM * IDIM);

    const float sa = STEP ? fmaxf(__int_as_float(g_maxh_bits), 1.0f) * (1.0f / QMAX)
                          : fmaxf(__int_as_float(g_maxx_bits), 1e-30f) * (1.0f / QMAX);
    for (int j = tid; j < BN; j += NT) {
        sdec[j] = STEP ? __expf(-DT / tau[n0 + j]) : (aux0[n0 + j] + aux1[n0 + j]);
        ssab[j] = sa * sbv[n0 + j];
    }

    const int lrow = ((lane >> 3) & 1) * 8 + (lane & 7);
    const int lkh  = (lane >> 4);

    // staging: 1536 16B chunks/stage, 6 per thread (A:1024, B:512)
    const int8_t* gptr[6];
    uint32_t sdst[6];
    #pragma unroll
    for (int t = 0; t < 6; t++) {
        int idx = tid + t * NT;
        if (idx < 1024) {
            int p = idx >> 9, rem = idx & 511, r = rem >> 2, j = rem & 3;
            sdst[t] = p * A_PLANE + (uint32_t)(r * 64 + ((j ^ ((r >> 1) & 3)) << 4));
            gptr[t] = Aq + (p ? aplane : 0) + (size_t)(m0 + r) * K + j * 16;
        } else {
            int q = idx - 1024;
            int p = q >> 8, rem = q & 255, r = rem >> 2, j = rem & 3;
            sdst[t] = OFF_BPL + p * B_PLANE + (uint32_t)(r * 64 + ((j ^ ((r >> 1) & 3)) << 4));
            gptr[t] = Wq + (p ? wplane : 0) + (size_t)(n0 + r) * K + j * 16;
        }
    }

    const int NK = K / BK;
    auto stage = [&](int i) {
        const uint32_t base = sb + (i % STAGES) * STAGE_BYTES;
        const int koff = i * BK;
        #pragma unroll
        for (int t = 0; t < 6; t++) cp16(base + sdst[t], gptr[t] + koff);
    };

    int s11[4][2][4], sxx[4][2][4];
    #pragma unroll
    for (int mt = 0; mt < 4; mt++)
        #pragma unroll
        for (int nt = 0; nt < 2; nt++)
            #pragma unroll
            for (int q = 0; q < 4; q++) { s11[mt][nt][q] = 0; sxx[mt][nt][q] = 0; }

    uint32_t aoff[4][2];
    #pragma unroll
    for (int mt = 0; mt < 4; mt++) {
        const int r = wm * 64 + mt * 16 + lrow;
        const int q = (r >> 1) & 3;
        #pragma unroll
        for (int ks = 0; ks < 2; ks++)
            aoff[mt][ks] = (uint32_t)(r * 64 + (((ks * 2 + lkh) ^ q) << 4));
    }
    uint32_t boff[2];
    {
        const int r = wn * 16 + lrow;
        const int q = (r >> 1) & 3;
        #pragma unroll
        for (int ks = 0; ks < 2; ks++)
            boff[ks] = OFF_BPL + (uint32_t)(r * 64 + (((ks * 2 + lkh) ^ q) << 4));
    }

    #pragma unroll
    for (int i = 0; i < STAGES - 1; i++)
        if (i < NK) { stage(i); cp_commit(); }

    for (int i = 0; i < NK; i++) {
        const int rem = NK - 1 - i;
        if      (rem >= 2) cp_wait<2>();
        else if (rem == 1) cp_wait<1>();
        else               cp_wait<0>();
        __syncthreads();
        if (i + STAGES - 1 < NK) { stage(i + STAGES - 1); cp_commit(); }

        const uint32_t stg = sb + (i % STAGES) * STAGE_BYTES;
        #pragma unroll
        for (int ks = 0; ks < 2; ks++) {
            uint32_t a1[4][4], a0[4][4], b1x[4], b0x[4];
            #pragma unroll
            for (int mt = 0; mt < 4; mt++) {
                ldsm4(a1[mt], stg + aoff[mt][ks]);
                ldsm4(a0[mt], stg + A_PLANE + aoff[mt][ks]);
            }
            ldsm4(b1x, stg + boff[ks]);
            ldsm4(b0x, stg + B_PLANE + boff[ks]);
            uint32_t b1n0[2] = { b1x[0], b1x[2] }, b1n1[2] = { b1x[1], b1x[3] };
            uint32_t b0n0[2] = { b0x[0], b0x[2] }, b0n1[2] = { b0x[1], b0x[3] };
            #pragma unroll
            for (int mt = 0; mt < 4; mt++) {      // q1*q1 -> s11
                imma(s11[mt][0], a1[mt], b1n0);
                imma(s11[mt][1], a1[mt], b1n1);
            }
            #pragma unroll
            for (int mt = 0; mt < 4; mt++) {      // q1*q0 -> sxx
                imma(sxx[mt][0], a1[mt], b0n0);
                imma(sxx[mt][1], a1[mt], b0n1);
            }
            #pragma unroll
            for (int mt = 0; mt < 4; mt++) {      // q0*q1 -> sxx
                imma(sxx[mt][0], a0[mt], b1n0);
                imma(sxx[mt][1], a0[mt], b1n1);
            }
        }
    }

    const float inv_sh = STEP ? (QMAX / fmaxf(__int_as_float(g_maxh_bits), 1.0f)) : 0.0f;
    const size_t outplane = (size_t)BDIM * HDIM;
    #pragma unroll
    for (int mt = 0; mt < 4; mt++) {
        #pragma unroll
        for (int h = 0; h < 2; h++) {
            const int row = m0 + wm * 64 + mt * 16 + g + h * 8;
            const size_t base = (size_t)row * ldo;
            #pragma unroll
            for (int nt = 0; nt < 2; nt++) {
                const int col = n0 + wn * 16 + nt * 8 + tig * 2;
                const float sc0 = ssab[col - n0];
                const float sc1 = ssab[col - n0 + 1];
                const float d0 = sc0 * fmaf(16384.0f, (float)s11[mt][nt][h * 2 + 0],
                                            128.0f * (float)sxx[mt][nt][h * 2 + 0]);
                const float d1 = sc1 * fmaf(16384.0f, (float)s11[mt][nt][h * 2 + 1],
                                            128.0f * (float)sxx[mt][nt][h * 2 + 1]);
                if (STEP) {
                    float2 ib = *reinterpret_cast<const float2*>(aux0 + base + col);
                    float2 hf = *reinterpret_cast<const float2*>(aux1 + base + col);
                    const float dc0 = sdec[col - n0];
                    const float dc1 = sdec[col - n0 + 1];
                    const float hn0 = dc0 * hf.x + (1.0f - dc0) * tanh_acc(d0 + ib.x);
                    const float hn1 = dc1 * hf.y + (1.0f - dc1) * tanh_acc(d1 + ib.y);
                    *reinterpret_cast<float2*>(out_full + base + col) = make_float2(hn0, hn1);
                    int8_t c1x, c1y, c0x, c0y;
                    quant1(hn0, inv_sh, c1x, c0x);
                    quant1(hn1, inv_sh, c1y, c0y);
                    out_q[base + col] = c1x;
                    out_q[base + col + 1] = c1y;
                    out_q[outplane + base + col] = c0x;
                    out_q[outplane + base + col + 1] = c0y;
                } else {
                    float2 o = make_float2(d0 + sdec[col - n0], d1 + sdec[col - n0 + 1]);
                    *reinterpret_cast<float2*>(out_full + base + col) = o;
                }
            }
        }
    }
}

extern "C" void kernel_launch(void* const* d_in, const int* in_sizes, int n_in,
                              void* d_out, int out_size) {
    (void)in_sizes; (void)n_in; (void)out_size;
    const float* x   = (const float*)d_in[0];
    const float* h0  = (const float*)d_in[1];
    const float* Wih = (const float*)d_in[2];
    const float* bih = (const float*)d_in[3];
    const float* Whh = (const float*)d_in[4];
    const float* bhh = (const float*)d_in[5];
    const float* tau = (const float*)d_in[6];
    float* out = (float*)d_out;

    float *p_ihb, *p_hfull, *p_swih, *p_swhh;
    int8_t *p_xq, *p_wihq, *p_whhq, *p_hqA, *p_hqB;
    cudaGetSymbolAddress((void**)&p_ihb, g_ihb);
    cudaGetSymbolAddress((void**)&p_hfull, g_hfull);
    cudaGetSymbolAddress((void**)&p_swih, g_swih);
    cudaGetSymbolAddress((void**)&p_swhh, g_swhh);
    cudaGetSymbolAddress((void**)&p_xq, g_xq);
    cudaGetSymbolAddress((void**)&p_wihq, g_wihq);
    cudaGetSymbolAddress((void**)&p_whhq, g_whhq);
    cudaGetSymbolAddress((void**)&p_hqA, g_hqA);
    cudaGetSymbolAddress((void**)&p_hqB, g_hqB);

    cudaFuncSetAttribute(gemm_kernel<false>, cudaFuncAttributeMaxDynamicSharedMemorySize, SMEM_TOTAL);
    cudaFuncSetAttribute(gemm_kernel<true>,  cudaFuncAttributeMaxDynamicSharedMemorySize, SMEM_TOTAL);

    init_scales_kernel<<<1, 32>>>();
    reduce_scales_kernel<<<512, 256>>>(x, h0, Wih, Whh);
    quant_all_kernel<<<512, 256>>>(x, h0, Wih, Whh);

    dim3 grid(HDIM / BN, BDIM / BM);
    // ih = x @ Wih^T + b_ih + b_hh (biases folded)
    gemm_kernel<false><<<grid, NT, SMEM_TOTAL>>>(p_xq, p_wihq, IDIM,
                                                 bih, bhh, nullptr, p_swih,
                                                 p_ihb, nullptr, HDIM);
    int8_t *q_in = p_hqA, *q_out = p_hqB;
    for (int s = 0; s < NSTEPS; s++) {
        float* full_dst = (s == NSTEPS - 1) ? out : p_hfull;
        gemm_kernel<true><<<grid, NT, SMEM_TOTAL>>>(q_in, p_whhq, HDIM,
                                                    p_ihb, p_hfull, tau, p_swhh,
                                                    full_dst, q_out, HDIM);
        int8_t* t = q_in; q_in = q_out; q_out = t;
    }
}

// round 10
// speedup vs baseline: 1.5390x; 1.5390x over previous
#include <cuda_runtime.h>
#include <cuda_bf16.h>
#include <cstdint>

static constexpr int BDIM = 4096;
static constexpr int IDIM = 1024;
static constexpr int HDIM = 2048;
static constexpr int NSTEPS = 10;
static constexpr float DT = 0.1f;

static constexpr int BM = 256, BN = 128, BK = 32;
static constexpr int STAGES = 4;
static constexpr int NT = 512;
// stage: [A_hi 16K | A_lo 16K | B_hi 8K | B_lo 8K] = 48 KB
static constexpr int A_PLANE = BM * BK * 2;            // 16 KB
static constexpr int B_PLANE = BN * BK * 2;            // 8 KB
static constexpr int OFF_B = 2 * A_PLANE;              // 32 KB
static constexpr int STAGE_BYTES = 2 * A_PLANE + 2 * B_PLANE;   // 48 KB
static constexpr int OFF_COLV = STAGES * STAGE_BYTES;  // 192 KB
static constexpr int SMEM_TOTAL = OFF_COLV + BN * 4 + 16;

__device__ float g_ihb  [BDIM * HDIM];
__device__ float g_hfull[BDIM * HDIM];
__device__ __nv_bfloat16 g_hhiA[BDIM * HDIM];
__device__ __nv_bfloat16 g_hloA[BDIM * HDIM];
__device__ __nv_bfloat16 g_hhiB[BDIM * HDIM];
__device__ __nv_bfloat16 g_hloB[BDIM * HDIM];
__device__ __nv_bfloat16 g_xhi [BDIM * IDIM];
__device__ __nv_bfloat16 g_xlo [BDIM * IDIM];
__device__ __nv_bfloat16 g_wihhi[HDIM * IDIM];
__device__ __nv_bfloat16 g_wihlo[HDIM * IDIM];
__device__ __nv_bfloat16 g_whhhi[HDIM * HDIM];
__device__ __nv_bfloat16 g_whhlo[HDIM * HDIM];

__device__ __forceinline__ uint32_t smem_u32(const void* p) {
    uint32_t a;
    asm("{ .reg .u64 t; cvta.to.shared.u64 t, %1; cvt.u32.u64 %0, t; }" : "=r"(a) : "l"(p));
    return a;
}
__device__ __forceinline__ void cp16(uint32_t dst, const void* src) {
    asm volatile("cp.async.cg.shared.global [%0], [%1], 16;" :: "r"(dst), "l"(src) : "memory");
}
__device__ __forceinline__ void cp_commit() { asm volatile("cp.async.commit_group;" ::: "memory"); }
template <int N> __device__ __forceinline__ void cp_wait() {
    asm volatile("cp.async.wait_group %0;" :: "n"(N) : "memory");
}
__device__ __forceinline__ float tanh_acc(float x) {
    float ax = fabsf(x);
    float e = __expf(-2.0f * ax);
    float t = (1.0f - e) / (1.0f + e);
    return copysignf(t, x);
}
__device__ __forceinline__ void mma_bf16(float* c, const uint32_t* a, const uint32_t* b) {
    asm volatile(
        "mma.sync.aligned.m16n8k16.row.col.f32.bf16.bf16.f32 "
        "{%0,%1,%2,%3},{%4,%5,%6,%7},{%8,%9},{%0,%1,%2,%3};"
        : "+f"(c[0]), "+f"(c[1]), "+f"(c[2]), "+f"(c[3])
        : "r"(a[0]), "r"(a[1]), "r"(a[2]), "r"(a[3]), "r"(b[0]), "r"(b[1]));
}
__device__ __forceinline__ void ldsm4(uint32_t* r, uint32_t addr) {
    asm volatile("ldmatrix.sync.aligned.m8n8.x4.shared.b16 {%0,%1,%2,%3}, [%4];"
                 : "=r"(r[0]), "=r"(r[1]), "=r"(r[2]), "=r"(r[3]) : "r"(addr));
}
__device__ __forceinline__ void split1(float v, __nv_bfloat16& h, __nv_bfloat16& l) {
    h = __float2bfloat16(v);
    l = __float2bfloat16(v - __bfloat162float(h));
}

__global__ void prep_all_kernel(const float* __restrict__ x,
                                const float* __restrict__ Wih,
                                const float* __restrict__ Whh,
                                const float* __restrict__ h0,
                                __nv_bfloat16* __restrict__ xhi, __nv_bfloat16* __restrict__ xlo,
                                __nv_bfloat16* __restrict__ wihhi, __nv_bfloat16* __restrict__ wihlo,
                                __nv_bfloat16* __restrict__ whhhi, __nv_bfloat16* __restrict__ whhlo,
                                float* __restrict__ hfull,
                                __nv_bfloat16* __restrict__ hhi, __nv_bfloat16* __restrict__ hlo) {
    const int stride = gridDim.x * blockDim.x;
    const int t0 = blockIdx.x * blockDim.x + threadIdx.x;
    auto split4 = [](float4 v, __nv_bfloat16* hi, __nv_bfloat16* lo, int i) {
        __nv_bfloat162 h01, h23, l01, l23;
        split1(v.x, h01.x, l01.x); split1(v.y, h01.y, l01.y);
        split1(v.z, h23.x, l23.x); split1(v.w, h23.y, l23.y);
        reinterpret_cast<__nv_bfloat162*>(hi)[i * 2]     = h01;
        reinterpret_cast<__nv_bfloat162*>(hi)[i * 2 + 1] = h23;
        reinterpret_cast<__nv_bfloat162*>(lo)[i * 2]     = l01;
        reinterpret_cast<__nv_bfloat162*>(lo)[i * 2 + 1] = l23;
    };
    for (int i = t0; i < BDIM * IDIM / 4; i += stride)
        split4(reinterpret_cast<const float4*>(x)[i], xhi, xlo, i);
    for (int i = t0; i < HDIM * IDIM / 4; i += stride)
        split4(reinterpret_cast<const float4*>(Wih)[i], wihhi, wihlo, i);
    for (int i = t0; i < HDIM * HDIM / 4; i += stride)
        split4(reinterpret_cast<const float4*>(Whh)[i], whhhi, whhlo, i);
    for (int i = t0; i < BDIM * HDIM / 4; i += stride) {
        float4 v = reinterpret_cast<const float4*>(h0)[i];
        reinterpret_cast<float4*>(hfull)[i] = v;
        split4(v, hhi, hlo, i);
    }
}

// D[m][n] = sum_k A[m][k]*W[n][k]; bf16x3 (hh + hl + lh), fp32 acc.
template <bool STEP>
__global__ __launch_bounds__(NT, 1)
void gemm_kernel(const __nv_bfloat16* __restrict__ Ahi, const __nv_bfloat16* __restrict__ Alo,
                 const __nv_bfloat16* __restrict__ Whi, const __nv_bfloat16* __restrict__ Wlo,
                 int K,
                 const float* __restrict__ aux0,   // STEP: ihb      | !STEP: b_ih
                 const float* __restrict__ aux1,   // STEP: hfull_in | !STEP: b_hh
                 const float* __restrict__ tau,
                 float* __restrict__ out_full,
                 __nv_bfloat16* __restrict__ out_hi, __nv_bfloat16* __restrict__ out_lo,
                 int ldo) {
    extern __shared__ char sm[];
    float* colv = (float*)(sm + OFF_COLV);
    const uint32_t sb = smem_u32(sm);
    const int tid = threadIdx.x;
    const int lane = tid & 31;
    const int wid = tid >> 5;
    const int wm = wid >> 2;      // 0..3 -> 64 rows of M each
    const int wn = wid & 3;       // 0..3 -> 32 cols of N each
    const int g = lane >> 2;
    const int tig = lane & 3;
    const int n0 = blockIdx.x * BN;
    const int m0 = blockIdx.y * BM;

    for (int j = tid; j < BN; j += NT)
        colv[j] = STEP ? __expf(-DT / tau[n0 + j]) : (aux0[n0 + j] + aux1[n0 + j]);

    // ---- staging: 3072 16B chunks/stage (A:2048, B:1024), 6 per thread ----
    const char* gsrc[6];
    uint32_t sdst[6];
    #pragma unroll
    for (int t = 0; t < 6; t++) {
        int idx = tid + t * NT;
        if (idx < 2048) {
            int p = idx >> 10, rem = idx & 1023, r = rem >> 2, j = rem & 3;
            sdst[t] = p * A_PLANE + (uint32_t)(r * 64 + ((j ^ ((r >> 1) & 3)) << 4));
            gsrc[t] = (const char*)(p ? Alo : Ahi) + ((size_t)(m0 + r) * K + j * 8) * 2;
        } else {
            int q = idx - 2048;
            int p = q >> 9, rem = q & 511, r = rem >> 2, j = rem & 3;
            sdst[t] = OFF_B + p * B_PLANE + (uint32_t)(r * 64 + ((j ^ ((r >> 1) & 3)) << 4));
            gsrc[t] = (const char*)(p ? Wlo : Whi) + ((size_t)(n0 + r) * K + j * 8) * 2;
        }
    }

    const int NK = K / BK;
    auto stage = [&](int i) {
        const uint32_t base = sb + (i % STAGES) * STAGE_BYTES;
        const int koff = i * BK * 2;
        #pragma unroll
        for (int t = 0; t < 6; t++) cp16(base + sdst[t], gsrc[t] + koff);
    };

    // ---- ldmatrix geometry ----
    const int lrow = ((lane >> 3) & 1) * 8 + (lane & 7);
    const int lkh  = (lane >> 4);
    uint32_t aO, bO;
    {
        const int rA = wm * 64 + lrow;
        aO = (uint32_t)(rA * 64 + ((lkh ^ ((rA >> 1) & 3)) << 4));
        const int rB = wn * 32 + lrow;
        bO = (uint32_t)(OFF_B + rB * 64 + ((lkh ^ ((rB >> 1) & 3)) << 4));
    }

    float acc[4][4][4];
    #pragma unroll
    for (int mt = 0; mt < 4; mt++)
        #pragma unroll
        for (int nt = 0; nt < 4; nt++)
            #pragma unroll
            for (int q = 0; q < 4; q++) acc[mt][nt][q] = 0.0f;

    #pragma unroll
    for (int i = 0; i < STAGES - 1; i++)
        if (i < NK) { stage(i); cp_commit(); }

    for (int i = 0; i < NK; i++) {
        const int rem = NK - 1 - i;
        if      (rem >= 2) cp_wait<2>();
        else if (rem == 1) cp_wait<1>();
        else               cp_wait<0>();
        __syncthreads();
        if (i + STAGES - 1 < NK) { stage(i + STAGES - 1); cp_commit(); }

        const uint32_t stg = sb + (i % STAGES) * STAGE_BYTES;
        #pragma unroll
        for (int ks = 0; ks < 2; ks++) {
            const uint32_t kx = (uint32_t)(ks << 5);
            uint32_t bh0x[4], bh1x[4], bl0x[4], bl1x[4];
            ldsm4(bh0x, stg + (bO ^ kx));
            ldsm4(bh1x, stg + ((bO + 1024) ^ kx));
            ldsm4(bl0x, stg + B_PLANE + (bO ^ kx));
            ldsm4(bl1x, stg + B_PLANE + ((bO + 1024) ^ kx));
            uint32_t b0h[2] = { bh0x[0], bh0x[2] }, b1h[2] = { bh0x[1], bh0x[3] };
            uint32_t b2h[2] = { bh1x[0], bh1x[2] }, b3h[2] = { bh1x[1], bh1x[3] };
            uint32_t b0l[2] = { bl0x[0], bl0x[2] }, b1l[2] = { bl0x[1], bl0x[3] };
            uint32_t b2l[2] = { bl1x[0], bl1x[2] }, b3l[2] = { bl1x[1], bl1x[3] };
            uint32_t ah[4][4], al[4][4];
            #pragma unroll
            for (int mt = 0; mt < 4; mt++) {
                const uint32_t am = (aO + mt * 1024) ^ kx;
                ldsm4(ah[mt], stg + am);
                ldsm4(al[mt], stg + A_PLANE + am);
            }
            #pragma unroll
            for (int mt = 0; mt < 4; mt++) {      // hh
                mma_bf16(acc[mt][0], ah[mt], b0h);
                mma_bf16(acc[mt][1], ah[mt], b1h);
                mma_bf16(acc[mt][2], ah[mt], b2h);
                mma_bf16(acc[mt][3], ah[mt], b3h);
            }
            #pragma unroll
            for (int mt = 0; mt < 4; mt++) {      // hl
                mma_bf16(acc[mt][0], ah[mt], b0l);
                mma_bf16(acc[mt][1], ah[mt], b1l);
                mma_bf16(acc[mt][2], ah[mt], b2l);
                mma_bf16(acc[mt][3], ah[mt], b3l);
            }
            #pragma unroll
            for (int mt = 0; mt < 4; mt++) {      // lh
                mma_bf16(acc[mt][0], al[mt], b0h);
                mma_bf16(acc[mt][1], al[mt], b1h);
                mma_bf16(acc[mt][2], al[mt], b2h);
                mma_bf16(acc[mt][3], al[mt], b3h);
            }
        }
    }

    #pragma unroll
    for (int mt = 0; mt < 4; mt++) {
        #pragma unroll
        for (int h = 0; h < 2; h++) {
            const int row = m0 + wm * 64 + mt * 16 + g + h * 8;
            const size_t base = (size_t)row * ldo;
            #pragma unroll
            for (int nt = 0; nt < 4; nt++) {
                const int col = n0 + wn * 32 + nt * 8 + tig * 2;
                const float d0 = acc[mt][nt][h * 2 + 0];
                const float d1 = acc[mt][nt][h * 2 + 1];
                if (STEP) {
                    float2 ib = *reinterpret_cast<const float2*>(aux0 + base + col);
                    float2 hf = *reinterpret_cast<const float2*>(aux1 + base + col);
                    const float dc0 = colv[col - n0];
                    const float dc1 = colv[col - n0 + 1];
                    const float hn0 = dc0 * hf.x + (1.0f - dc0) * tanh_acc(d0 + ib.x);
                    const float hn1 = dc1 * hf.y + (1.0f - dc1) * tanh_acc(d1 + ib.y);
                    *reinterpret_cast<float2*>(out_full + base + col) = make_float2(hn0, hn1);
                    __nv_bfloat162 hp, lp;
                    split1(hn0, hp.x, lp.x);
                    split1(hn1, hp.y, lp.y);
                    *reinterpret_cast<__nv_bfloat162*>(out_hi + base + col) = hp;
                    *reinterpret_cast<__nv_bfloat162*>(out_lo + base + col) = lp;
                } else {
                    float2 o = make_float2(d0 + colv[col - n0], d1 + colv[col - n0 + 1]);
                    *reinterpret_cast<float2*>(out_full + base + col) = o;
                }
            }
        }
    }
}

extern "C" void kernel_launch(void* const* d_in, const int* in_sizes, int n_in,
                              void* d_out, int out_size) {
    (void)in_sizes; (void)n_in; (void)out_size;
    const float* x   = (const float*)d_in[0];
    const float* h0  = (const float*)d_in[1];
    const float* Wih = (const float*)d_in[2];
    const float* bih = (const float*)d_in[3];
    const float* Whh = (const float*)d_in[4];
    const float* bhh = (const float*)d_in[5];
    const float* tau = (const float*)d_in[6];
    float* out = (float*)d_out;

    float *p_ihb, *p_hfull;
    __nv_bfloat16 *p_hhiA, *p_hloA, *p_hhiB, *p_hloB;
    __nv_bfloat16 *p_xhi, *p_xlo, *p_wihhi, *p_wihlo, *p_whhhi, *p_whhlo;
    cudaGetSymbolAddress((void**)&p_ihb, g_ihb);
    cudaGetSymbolAddress((void**)&p_hfull, g_hfull);
    cudaGetSymbolAddress((void**)&p_hhiA, g_hhiA);
    cudaGetSymbolAddress((void**)&p_hloA, g_hloA);
    cudaGetSymbolAddress((void**)&p_hhiB, g_hhiB);
    cudaGetSymbolAddress((void**)&p_hloB, g_hloB);
    cudaGetSymbolAddress((void**)&p_xhi, g_xhi);
    cudaGetSymbolAddress((void**)&p_xlo, g_xlo);
    cudaGetSymbolAddress((void**)&p_wihhi, g_wihhi);
    cudaGetSymbolAddress((void**)&p_wihlo, g_wihlo);
    cudaGetSymbolAddress((void**)&p_whhhi, g_whhhi);
    cudaGetSymbolAddress((void**)&p_whhlo, g_whhlo);

    cudaFuncSetAttribute(gemm_kernel<false>, cudaFuncAttributeMaxDynamicSharedMemorySize, SMEM_TOTAL);
    cudaFuncSetAttribute(gemm_kernel<true>,  cudaFuncAttributeMaxDynamicSharedMemorySize, SMEM_TOTAL);

    prep_all_kernel<<<512, 256>>>(x, Wih, Whh, h0,
                                  p_xhi, p_xlo, p_wihhi, p_wihlo, p_whhhi, p_whhlo,
                                  p_hfull, p_hhiA, p_hloA);

    dim3 grid(HDIM / BN, BDIM / BM);   // 16 x 16 = 256 CTAs
    gemm_kernel<false><<<grid, NT, SMEM_TOTAL>>>(p_xhi, p_xlo, p_wihhi, p_wihlo, IDIM,
                                                 bih, bhh, nullptr,
                                                 p_ihb, nullptr, nullptr, HDIM);
    __nv_bfloat16 *hi_in = p_hhiA, *lo_in = p_hloA;
    __nv_bfloat16 *hi_out = p_hhiB, *lo_out = p_hloB;
    for (int s = 0; s < NSTEPS; s++) {
        float* full_dst = (s == NSTEPS - 1) ? out : p_hfull;
        gemm_kernel<true><<<grid, NT, SMEM_TOTAL>>>(hi_in, lo_in, p_whhhi, p_whhlo, HDIM,
                                                    p_ihb, p_hfull, tau,
                                                    full_dst, hi_out, lo_out, HDIM);
        __nv_bfloat16* t;
        t = hi_in; hi_in = hi_out; hi_out = t;
        t = lo_in; lo_in = lo_out; lo_out = t;
    }
}

// round 11
// speedup vs baseline: 2.4086x; 1.5650x over previous
#include <cuda_runtime.h>
#include <cuda_bf16.h>
#include <cstdint>

static constexpr int BDIM = 4096;
static constexpr int IDIM = 1024;
static constexpr int HDIM = 2048;
static constexpr int NSTEPS = 10;
static constexpr float DT = 0.1f;

static constexpr int BM = 128, BN = 64, BK = 32;
static constexpr int STAGES = 3;
static constexpr int NT = 256;
// stage: [A_hi 8K | A_lo 8K | B_hi 4K | B_lo 4K] = 24 KB
static constexpr int A_PLANE = BM * BK * 2;            // 8 KB
static constexpr int B_PLANE = BN * BK * 2;            // 4 KB
static constexpr int STAGE_BYTES = 2 * A_PLANE + 2 * B_PLANE;   // 24 KB
static constexpr int OFF_BPL = 2 * A_PLANE;            // 16 KB into stage
static constexpr int OFF_COLV = STAGES * STAGE_BYTES;  // 72 KB
static constexpr int SMEM_TOTAL = OFF_COLV + BN * 4 + 16;   // ~72.3 KB -> 3 CTAs/SM

__device__ float g_ihb  [BDIM * HDIM];
__device__ float g_hfull[BDIM * HDIM];
__device__ __nv_bfloat16 g_hhiA[BDIM * HDIM];
__device__ __nv_bfloat16 g_hloA[BDIM * HDIM];
__device__ __nv_bfloat16 g_hhiB[BDIM * HDIM];
__device__ __nv_bfloat16 g_hloB[BDIM * HDIM];
__device__ __nv_bfloat16 g_xhi [BDIM * IDIM];
__device__ __nv_bfloat16 g_xlo [BDIM * IDIM];
__device__ __nv_bfloat16 g_wihhi[HDIM * IDIM];
__device__ __nv_bfloat16 g_wihlo[HDIM * IDIM];
__device__ __nv_bfloat16 g_whhhi[HDIM * HDIM];
__device__ __nv_bfloat16 g_whhlo[HDIM * HDIM];

__device__ __forceinline__ uint32_t smem_u32(const void* p) {
    uint32_t a;
    asm("{ .reg .u64 t; cvta.to.shared.u64 t, %1; cvt.u32.u64 %0, t; }" : "=r"(a) : "l"(p));
    return a;
}
__device__ __forceinline__ void cp16(uint32_t dst, const void* src) {
    asm volatile("cp.async.cg.shared.global [%0], [%1], 16;" :: "r"(dst), "l"(src) : "memory");
}
__device__ __forceinline__ void cp_commit() { asm volatile("cp.async.commit_group;" ::: "memory"); }
template <int N> __device__ __forceinline__ void cp_wait() {
    asm volatile("cp.async.wait_group %0;" :: "n"(N) : "memory");
}
__device__ __forceinline__ float tanh_acc(float x) {
    float ax = fabsf(x);
    float e = __expf(-2.0f * ax);
    float t = (1.0f - e) / (1.0f + e);
    return copysignf(t, x);
}
__device__ __forceinline__ void mma_bf16(float* c, const uint32_t* a, const uint32_t* b) {
    asm volatile(
        "mma.sync.aligned.m16n8k16.row.col.f32.bf16.bf16.f32 "
        "{%0,%1,%2,%3},{%4,%5,%6,%7},{%8,%9},{%0,%1,%2,%3};"
        : "+f"(c[0]), "+f"(c[1]), "+f"(c[2]), "+f"(c[3])
        : "r"(a[0]), "r"(a[1]), "r"(a[2]), "r"(a[3]), "r"(b[0]), "r"(b[1]));
}
__device__ __forceinline__ void ldsm4(uint32_t* r, uint32_t addr) {
    asm volatile("ldmatrix.sync.aligned.m8n8.x4.shared.b16 {%0,%1,%2,%3}, [%4];"
                 : "=r"(r[0]), "=r"(r[1]), "=r"(r[2]), "=r"(r[3]) : "r"(addr));
}
__device__ __forceinline__ void split1(float v, __nv_bfloat16& h, __nv_bfloat16& l) {
    h = __float2bfloat16(v);
    l = __float2bfloat16(v - __bfloat162float(h));
}

// One prep kernel: split x / Wih / Whh, copy+split h0.
__global__ void prep_all_kernel(const float* __restrict__ x,
                                const float* __restrict__ Wih,
                                const float* __restrict__ Whh,
                                const float* __restrict__ h0,
                                __nv_bfloat16* __restrict__ xhi, __nv_bfloat16* __restrict__ xlo,
                                __nv_bfloat16* __restrict__ wihhi, __nv_bfloat16* __restrict__ wihlo,
                                __nv_bfloat16* __restrict__ whhhi, __nv_bfloat16* __restrict__ whhlo,
                                float* __restrict__ hfull,
                                __nv_bfloat16* __restrict__ hhi, __nv_bfloat16* __restrict__ hlo) {
    const int stride = gridDim.x * blockDim.x;
    const int t0 = blockIdx.x * blockDim.x + threadIdx.x;
    auto split4 = [](float4 v, __nv_bfloat16* hi, __nv_bfloat16* lo, int i) {
        __nv_bfloat162 h01, h23, l01, l23;
        split1(v.x, h01.x, l01.x); split1(v.y, h01.y, l01.y);
        split1(v.z, h23.x, l23.x); split1(v.w, h23.y, l23.y);
        reinterpret_cast<__nv_bfloat162*>(hi)[i * 2]     = h01;
        reinterpret_cast<__nv_bfloat162*>(hi)[i * 2 + 1] = h23;
        reinterpret_cast<__nv_bfloat162*>(lo)[i * 2]     = l01;
        reinterpret_cast<__nv_bfloat162*>(lo)[i * 2 + 1] = l23;
    };
    for (int i = t0; i < BDIM * IDIM / 4; i += stride)
        split4(reinterpret_cast<const float4*>(x)[i], xhi, xlo, i);
    for (int i = t0; i < HDIM * IDIM / 4; i += stride)
        split4(reinterpret_cast<const float4*>(Wih)[i], wihhi, wihlo, i);
    for (int i = t0; i < HDIM * HDIM / 4; i += stride)
        split4(reinterpret_cast<const float4*>(Whh)[i], whhhi, whhlo, i);
    for (int i = t0; i < BDIM * HDIM / 4; i += stride) {
        float4 v = reinterpret_cast<const float4*>(h0)[i];
        reinterpret_cast<float4*>(hfull)[i] = v;
        split4(v, hhi, hlo, i);
    }
}

// D[m][n] = sum_k A[m][k]*W[n][k]; bf16x3 (hh + hl + lh), fp32 acc.
template <bool STEP>
__global__ __launch_bounds__(NT, 3)
void gemm_kernel(const __nv_bfloat16* __restrict__ Ahi, const __nv_bfloat16* __restrict__ Alo,
                 const __nv_bfloat16* __restrict__ Whi, const __nv_bfloat16* __restrict__ Wlo,
                 int K,
                 const float* __restrict__ aux0,   // STEP: ihb      | !STEP: b_ih
                 const float* __restrict__ aux1,   // STEP: hfull_in | !STEP: b_hh
                 const float* __restrict__ tau,
                 float* __restrict__ out_full,
                 __nv_bfloat16* __restrict__ out_hi, __nv_bfloat16* __restrict__ out_lo,
                 int ldo) {
    extern __shared__ char sm[];
    float* colv = (float*)(sm + OFF_COLV);
    const uint32_t sb = smem_u32(sm);
    const int tid = threadIdx.x;
    const int lane = tid & 31;
    const int wid = tid >> 5;
    const int wm = wid >> 2;      // 0..1
    const int wn = wid & 3;       // 0..3
    const int g = lane >> 2;
    const int tig = lane & 3;
    const int n0 = blockIdx.x * BN;
    const int m0 = blockIdx.y * BM;

    for (int j = tid; j < BN; j += NT)
        colv[j] = STEP ? __expf(-DT / tau[n0 + j]) : (aux0[n0 + j] + aux1[n0 + j]);

    // ldmatrix lane geometry
    const int lrow = ((lane >> 3) & 1) * 8 + (lane & 7);
    const int lkh  = (lane >> 4);

    // staging: 1536 16B-chunks/stage (A:1024, B:512), 6 per thread
    const char* gsrc[6];
    uint32_t sdst[6];
    #pragma unroll
    for (int t = 0; t < 6; t++) {
        int idx = tid + t * NT;
        if (idx < 1024) {
            int p = idx >> 9, rem = idx & 511, r = rem >> 2, j = rem & 3;
            sdst[t] = p * A_PLANE + (uint32_t)(r * 64 + ((j ^ ((r >> 1) & 3)) << 4));
            gsrc[t] = (const char*)(p ? Alo : Ahi) + ((size_t)(m0 + r) * K + j * 8) * 2;
        } else {
            int q = idx - 1024;
            int p = q >> 8, rem = q & 255, r = rem >> 2, j = rem & 3;
            sdst[t] = OFF_BPL + p * B_PLANE + (uint32_t)(r * 64 + ((j ^ ((r >> 1) & 3)) << 4));
            gsrc[t] = (const char*)(p ? Wlo : Whi) + ((size_t)(n0 + r) * K + j * 8) * 2;
        }
    }

    const int NK = K / BK;
    auto stage = [&](int i, uint32_t base) {
        const int koff = i * BK * 2;
        #pragma unroll
        for (int t = 0; t < 6; t++) cp16(base + sdst[t], gsrc[t] + koff);
    };

    float acc[4][2][4];
    #pragma unroll
    for (int mt = 0; mt < 4; mt++)
        #pragma unroll
        for (int nt = 0; nt < 2; nt++)
            #pragma unroll
            for (int q = 0; q < 4; q++) acc[mt][nt][q] = 0.0f;

    // per-lane swizzled LDSM offsets
    uint32_t aoff[4][2];   // [mt][ks]
    #pragma unroll
    for (int mt = 0; mt < 4; mt++) {
        const int r = wm * 64 + mt * 16 + lrow;
        const int q = (r >> 1) & 3;
        #pragma unroll
        for (int ks = 0; ks < 2; ks++) {
            const int j = ks * 2 + lkh;
            aoff[mt][ks] = (uint32_t)(r * 64 + ((j ^ q) << 4));
        }
    }
    uint32_t boff[2];      // [ks]
    {
        const int r = wn * 16 + lrow;
        const int q = (r >> 1) & 3;
        #pragma unroll
        for (int ks = 0; ks < 2; ks++) {
            const int j = ks * 2 + lkh;
            boff[ks] = OFF_BPL + (uint32_t)(r * 64 + ((j ^ q) << 4));
        }
    }

    stage(0, sb); cp_commit();
    stage(1, sb + STAGE_BYTES); cp_commit();

    uint32_t buf = 0;   // 0,1,2 rotating
    for (int i = 0; i < NK; i++) {
        if (i < NK - 1) cp_wait<1>(); else cp_wait<0>();
        __syncthreads();
        if (i + 2 < NK) {
            uint32_t nb = buf + 2; if (nb >= 3) nb -= 3;
            stage(i + 2, sb + nb * STAGE_BYTES);
            cp_commit();
        }
        const uint32_t stg = sb + buf * STAGE_BYTES;
        buf++; if (buf == 3) buf = 0;

        #pragma unroll
        for (int ks = 0; ks < 2; ks++) {
            uint32_t ah[4][4], al[4][4], bhx[4], blx[4];
            #pragma unroll
            for (int mt = 0; mt < 4; mt++) {
                ldsm4(ah[mt], stg + aoff[mt][ks]);
                ldsm4(al[mt], stg + A_PLANE + aoff[mt][ks]);
            }
            ldsm4(bhx, stg + boff[ks]);
            ldsm4(blx, stg + B_PLANE + boff[ks]);
            uint32_t bh0[2] = { bhx[0], bhx[2] }, bh1[2] = { bhx[1], bhx[3] };
            uint32_t bl0[2] = { blx[0], blx[2] }, bl1[2] = { blx[1], blx[3] };
            // term-major sweeps: same-accumulator reuse distance = 8 MMAs
            #pragma unroll
            for (int mt = 0; mt < 4; mt++) {      // hh
                mma_bf16(acc[mt][0], ah[mt], bh0);
                mma_bf16(acc[mt][1], ah[mt], bh1);
            }
            #pragma unroll
            for (int mt = 0; mt < 4; mt++) {      // hl
                mma_bf16(acc[mt][0], ah[mt], bl0);
                mma_bf16(acc[mt][1], ah[mt], bl1);
            }
            #pragma unroll
            for (int mt = 0; mt < 4; mt++) {      // lh
                mma_bf16(acc[mt][0], al[mt], bh0);
                mma_bf16(acc[mt][1], al[mt], bh1);
            }
        }
    }

    #pragma unroll
    for (int mt = 0; mt < 4; mt++) {
        #pragma unroll
        for (int h = 0; h < 2; h++) {
            const int row = m0 + wm * 64 + mt * 16 + g + h * 8;
            const size_t base = (size_t)row * ldo;
            #pragma unroll
            for (int nt = 0; nt < 2; nt++) {
                const int col = n0 + wn * 16 + nt * 8 + tig * 2;
                const float d0 = acc[mt][nt][h * 2 + 0];
                const float d1 = acc[mt][nt][h * 2 + 1];
                if (STEP) {
                    float2 ib = *reinterpret_cast<const float2*>(aux0 + base + col);
                    float2 hf = *reinterpret_cast<const float2*>(aux1 + base + col);
                    const float dc0 = colv[col - n0];
                    const float dc1 = colv[col - n0 + 1];
                    const float hn0 = dc0 * hf.x + (1.0f - dc0) * tanh_acc(d0 + ib.x);
                    const float hn1 = dc1 * hf.y + (1.0f - dc1) * tanh_acc(d1 + ib.y);
                    *reinterpret_cast<float2*>(out_full + base + col) = make_float2(hn0, hn1);
                    __nv_bfloat162 hp, lp;
                    split1(hn0, hp.x, lp.x);
                    split1(hn1, hp.y, lp.y);
                    *reinterpret_cast<__nv_bfloat162*>(out_hi + base + col) = hp;
                    *reinterpret_cast<__nv_bfloat162*>(out_lo + base + col) = lp;
                } else {
                    float2 o = make_float2(d0 + colv[col - n0], d1 + colv[col - n0 + 1]);
                    *reinterpret_cast<float2*>(out_full + base + col) = o;
                }
            }
        }
    }
}

extern "C" void kernel_launch(void* const* d_in, const int* in_sizes, int n_in,
                              void* d_out, int out_size) {
    (void)in_sizes; (void)n_in; (void)out_size;
    const float* x   = (const float*)d_in[0];
    const float* h0  = (const float*)d_in[1];
    const float* Wih = (const float*)d_in[2];
    const float* bih = (const float*)d_in[3];
    const float* Whh = (const float*)d_in[4];
    const float* bhh = (const float*)d_in[5];
    const float* tau = (const float*)d_in[6];
    float* out = (float*)d_out;

    float *p_ihb, *p_hfull;
    __nv_bfloat16 *p_hhiA, *p_hloA, *p_hhiB, *p_hloB;
    __nv_bfloat16 *p_xhi, *p_xlo, *p_wihhi, *p_wihlo, *p_whhhi, *p_whhlo;
    cudaGetSymbolAddress((void**)&p_ihb, g_ihb);
    cudaGetSymbolAddress((void**)&p_hfull, g_hfull);
    cudaGetSymbolAddress((void**)&p_hhiA, g_hhiA);
    cudaGetSymbolAddress((void**)&p_hloA, g_hloA);
    cudaGetSymbolAddress((void**)&p_hhiB, g_hhiB);
    cudaGetSymbolAddress((void**)&p_hloB, g_hloB);
    cudaGetSymbolAddress((void**)&p_xhi, g_xhi);
    cudaGetSymbolAddress((void**)&p_xlo, g_xlo);
    cudaGetSymbolAddress((void**)&p_wihhi, g_wihhi);
    cudaGetSymbolAddress((void**)&p_wihlo, g_wihlo);
    cudaGetSymbolAddress((void**)&p_whhhi, g_whhhi);
    cudaGetSymbolAddress((void**)&p_whhlo, g_whhlo);

    cudaFuncSetAttribute(gemm_kernel<false>, cudaFuncAttributeMaxDynamicSharedMemorySize, SMEM_TOTAL);
    cudaFuncSetAttribute(gemm_kernel<true>,  cudaFuncAttributeMaxDynamicSharedMemorySize, SMEM_TOTAL);

    prep_all_kernel<<<512, 256>>>(x, Wih, Whh, h0,
                                  p_xhi, p_xlo, p_wihhi, p_wihlo, p_whhhi, p_whhlo,
                                  p_hfull, p_hhiA, p_hloA);

    dim3 grid(HDIM / BN, BDIM / BM);   // 32 x 32 = 1024 CTAs
    gemm_kernel<false><<<grid, NT, SMEM_TOTAL>>>(p_xhi, p_xlo, p_wihhi, p_wihlo, IDIM,
                                                 bih, bhh, nullptr,
                                                 p_ihb, nullptr, nullptr, HDIM);
    __nv_bfloat16 *hi_in = p_hhiA, *lo_in = p_hloA;
    __nv_bfloat16 *hi_out = p_hhiB, *lo_out = p_hloB;
    for (int s = 0; s < NSTEPS; s++) {
        float* full_dst = (s == NSTEPS - 1) ? out : p_hfull;
        gemm_kernel<true><<<grid, NT, SMEM_TOTAL>>>(hi_in, lo_in, p_whhhi, p_whhlo, HDIM,
                                                    p_ihb, p_hfull, tau,
                                                    full_dst, hi_out, lo_out, HDIM);
        __nv_bfloat16* t;
        t = hi_in; hi_in = hi_out; hi_out = t;
        t = lo_in; lo_in = lo_out; lo_out = t;
    }
}